// round 14
// baseline (speedup 1.0000x reference)
#include <cuda_runtime.h>
#include <cuda_fp16.h>
#include <math.h>
#include <stdint.h>

// ===========================================================================
// Fused INR via warp-level mma.sync, fp16 weights/acts, fp32 accum.
// R13 = R12 (8 warps, warp = 64 neurons x 64 points) + 2-k-step-deep A
//       prefetch pipeline (A0..A3 live) so A-LDG L2 latency (262 cyc far-die)
//       is covered by ~512 cyc of MMA issue instead of ~256.
// ===========================================================================

#define OMEGA0    30.0f
#define TWO_PI_F  6.283185307179586f
#define THREADS   256

#define NTILES    (512 + 5 * 1024)      // 5632 (mt,ks) tiles total
#define PLANE_U32 (NTILES * 128)        // u32 per plane (tile=128 u32)

__device__ __align__(16) uint32_t g_wfrag[PLANE_U32];   // fp16 weight fragments

// ---- SMEM layout (bytes) ----
#define SM_WOUT  0                       // 1536 floats
#define SM_CS    6144                    // 192 floats
#define SM_BFF   6912                    // 384 floats
#define SM_P0    9216                    // act plane 0: 512 rows x 128B
#define SM_P1    (SM_P0 + 65536)         // act plane 1
#define SMEM_BYTES (SM_P1 + 65536)       // 140288

// ---------------- helpers ----------------
__device__ __forceinline__ uint32_t smem_u32(const void* p) {
    uint32_t a;
    asm("{ .reg .u64 t; cvta.to.shared.u64 t, %1; cvt.u32.u64 %0, t; }"
        : "=r"(a) : "l"(p));
    return a;
}
__device__ __forceinline__ void mma16816(float* d, const uint4& a,
                                         uint32_t b0, uint32_t b1) {
    asm volatile(
        "mma.sync.aligned.m16n8k16.row.col.f32.f16.f16.f32 "
        "{%0,%1,%2,%3}, {%4,%5,%6,%7}, {%8,%9}, {%0,%1,%2,%3};"
        : "+f"(d[0]), "+f"(d[1]), "+f"(d[2]), "+f"(d[3])
        : "r"(a.x), "r"(a.y), "r"(a.z), "r"(a.w), "r"(b0), "r"(b1));
}
__device__ __forceinline__ void ldmx4t(uint32_t& r0, uint32_t& r1,
                                       uint32_t& r2, uint32_t& r3,
                                       uint32_t addr) {
    asm volatile(
        "ldmatrix.sync.aligned.m8n8.x4.trans.shared.b16 {%0,%1,%2,%3}, [%4];"
        : "=r"(r0), "=r"(r1), "=r"(r2), "=r"(r3) : "r"(addr));
}
__device__ __forceinline__ uint16_t hfb(float v) {
    __half h = __float2half_rn(v);
    return *reinterpret_cast<uint16_t*>(&h);
}
__device__ __forceinline__ float hff(uint16_t b) {
    __half h = *reinterpret_cast<__half*>(&b);
    return __half2float(h);
}

// store v (fp16) to (row, col n) in a plane, swizzled
__device__ __forceinline__ void store1(unsigned char* plane, int row, int n, float v) {
    uint32_t off = (uint32_t)row * 128u + (((uint32_t)n * 2u) ^ (((uint32_t)row & 7u) << 4));
    *(uint16_t*)(plane + off) = hfb(v);
}

// ---------------- weight prep: fp32 -> fragment-ordered fp16 ----------------
__global__ void prep_weights(const float* __restrict__ Wf,
                             const float* __restrict__ Wh) {
    int idx = blockIdx.x * blockDim.x + threadIdx.x;
    if (idx >= PLANE_U32) return;
    int tile = idx >> 7;
    int li   = idx & 127;
    int lane = li >> 2, q = li & 3;

    const float* src; int K, mt, ks;
    if (tile < 512) { mt = tile >> 4; ks = tile & 15; K = 256; src = Wf; }
    else {
        int th = tile - 512;
        int l = th >> 10, tt = th & 1023;
        mt = tt >> 5; ks = tt & 31; K = 512;
        src = Wh + (size_t)l * 512 * 512;
    }
    int r  = lane >> 2, c2 = (lane & 3) * 2;
    int row = mt * 16 + r + (q & 1) * 8;
    int k   = ks * 16 + c2 + (q >> 1) * 8;
    float w0 = src[(size_t)row * K + k];
    float w1 = src[(size_t)row * K + k + 1];
    g_wfrag[idx] = ((uint32_t)hfb(w1) << 16) | (uint32_t)hfb(w0);
}

// ---------------- one sine layer: src plane -> dst plane ----------------
template <int KS>
__device__ __forceinline__ void run_layer(
    unsigned char* dst, uint32_t src_u32,
    const uint32_t* __restrict__ whi,
    const float* __restrict__ bias,
    int wid, int lane)
{
    float acc[4][8][4];     // [m-tile][n-tile][frag]
#pragma unroll
    for (int a = 0; a < 4; ++a)
#pragma unroll
        for (int b = 0; b < 8; ++b)
#pragma unroll
            for (int c = 0; c < 4; ++c) acc[a][b][c] = 0.0f;

    const int r  = lane >> 2;
    const int cq = lane & 3;
    const int mid  = lane >> 3;
    const int rrow = lane & 7;
    const uint32_t rswz = (uint32_t)rrow << 4;
    const uint32_t krow_off = ((uint32_t)((mid & 1) * 8 + rrow)) * 128u;
    const uint32_t nb_base  = (uint32_t)((mid >> 1) * 8) * 2u;

    const uint32_t* pA[4];
#pragma unroll
    for (int mt = 0; mt < 4; ++mt)
        pA[mt] = whi + (size_t)((wid * 4 + mt) * KS) * 128 + lane * 4;

    uint32_t baddr[4];
#pragma unroll
    for (int j = 0; j < 4; ++j)
        baddr[j] = src_u32 + krow_off + (((uint32_t)j * 32u + nb_base) ^ rswz);

    // prologue: A for ks=0,1; B for ks=0
    uint4 A0[4], A1[4], A2[4], A3[4];
#pragma unroll
    for (int mt = 0; mt < 4; ++mt) {
        A0[mt] = *(const uint4*)pA[mt];
        A1[mt] = *(const uint4*)(pA[mt] + 128);
    }
    uint32_t B0[16], B1[16];
#pragma unroll
    for (int j = 0; j < 4; ++j)
        ldmx4t(B0[4 * j], B0[4 * j + 1], B0[4 * j + 2], B0[4 * j + 3],
               baddr[j]);

#pragma unroll 1
    for (int ks = 0; ks < KS; ks += 2) {
        // ---- even step: B(ks+1), A(ks+2); MMA on A0,B0 ----
        {
            const uint32_t kb = (uint32_t)(ks + 1) * 2048u;
#pragma unroll
            for (int j = 0; j < 4; ++j)
                ldmx4t(B1[4 * j], B1[4 * j + 1], B1[4 * j + 2], B1[4 * j + 3],
                       baddr[j] + kb);
        }
        if (ks + 2 < KS) {
#pragma unroll
            for (int mt = 0; mt < 4; ++mt)
                A2[mt] = *(const uint4*)(pA[mt] + (ks + 2) * 128);
        }
#pragma unroll
        for (int nt = 0; nt < 8; ++nt)
#pragma unroll
            for (int mt = 0; mt < 4; ++mt)
                mma16816(acc[mt][nt], A0[mt], B0[nt * 2], B0[nt * 2 + 1]);

        // ---- odd step: B(ks+2), A(ks+3); MMA on A1,B1 ----
        if (ks + 2 < KS) {
            const uint32_t kb = (uint32_t)(ks + 2) * 2048u;
#pragma unroll
            for (int j = 0; j < 4; ++j)
                ldmx4t(B0[4 * j], B0[4 * j + 1], B0[4 * j + 2], B0[4 * j + 3],
                       baddr[j] + kb);
        }
        if (ks + 3 < KS) {
#pragma unroll
            for (int mt = 0; mt < 4; ++mt)
                A3[mt] = *(const uint4*)(pA[mt] + (ks + 3) * 128);
        }
#pragma unroll
        for (int nt = 0; nt < 8; ++nt)
#pragma unroll
            for (int mt = 0; mt < 4; ++mt)
                mma16816(acc[mt][nt], A1[mt], B1[nt * 2], B1[nt * 2 + 1]);

#pragma unroll
        for (int mt = 0; mt < 4; ++mt) { A0[mt] = A2[mt]; A1[mt] = A3[mt]; }
    }

    // ---- epilogue: sin -> f16x2 pack -> STS to dst ----
#pragma unroll
    for (int mtl = 0; mtl < 4; ++mtl) {
        const int row0 = wid * 64 + mtl * 16 + r;
        const int row1 = row0 + 8;
        const float ob0 = OMEGA0 * __ldg(bias + row0);
        const float ob1 = OMEGA0 * __ldg(bias + row1);
        const uint32_t sw0 = ((uint32_t)row0 & 7u) << 4;
        const uint32_t sw1 = ((uint32_t)row1 & 7u) << 4;
#pragma unroll
        for (int nt = 0; nt < 8; ++nt) {
            const int n = nt * 8 + cq * 2;
            float v00 = __sinf(fmaf(OMEGA0, acc[mtl][nt][0], ob0));
            float v01 = __sinf(fmaf(OMEGA0, acc[mtl][nt][1], ob0));
            float v10 = __sinf(fmaf(OMEGA0, acc[mtl][nt][2], ob1));
            float v11 = __sinf(fmaf(OMEGA0, acc[mtl][nt][3], ob1));
            uint32_t hp0, hp1;
            asm("cvt.rn.f16x2.f32 %0, %1, %2;"
                : "=r"(hp0) : "f"(v01), "f"(v00));
            asm("cvt.rn.f16x2.f32 %0, %1, %2;"
                : "=r"(hp1) : "f"(v11), "f"(v10));
            uint32_t off0 = (uint32_t)row0 * 128u + (((uint32_t)n * 2u) ^ sw0);
            uint32_t off1 = (uint32_t)row1 * 128u + (((uint32_t)n * 2u) ^ sw1);
            *(uint32_t*)(dst + off0) = hp0;
            *(uint32_t*)(dst + off1) = hp1;
        }
    }
    __syncthreads();   // dst visible; src free for reuse as next dst
}

// ---------------- main kernel ----------------
__global__ void __launch_bounds__(THREADS, 1)
inr_mma_kernel(const float* __restrict__ coords,
               const float* __restrict__ B_ff,
               const float* __restrict__ b_first,
               const float* __restrict__ b_hidden,
               const float* __restrict__ W_out,
               const float* __restrict__ b_out,
               float* __restrict__ out, int L)
{
    extern __shared__ unsigned char sm[];
    float* wout = (float*)(sm + SM_WOUT);
    float* cs   = (float*)(sm + SM_CS);
    float* bff  = (float*)(sm + SM_BFF);
    unsigned char* p0 = sm + SM_P0;
    unsigned char* p1 = sm + SM_P1;
    const uint32_t p0u = smem_u32(p0);
    const uint32_t p1u = smem_u32(p1);

    const int tid  = threadIdx.x;
    const int wid  = tid >> 5;
    const int lane = tid & 31;
    const int pt0  = blockIdx.x * 64;

    if (tid < 192) {
        int g = pt0 * 3 + tid;
        cs[tid] = (g < L * 3) ? coords[g] : 0.0f;
    }
    for (int i = tid; i < 384; i += THREADS) bff[i] = B_ff[i];
    __syncthreads();

    // Fourier features -> plane 0. sin(2*pi*t) == sin(2*pi*(t - rint(t))).
    for (int e = tid; e < 8192; e += THREADS) {
        int j = e >> 6, m = e & 63;
        float t = cs[m * 3 + 0] * bff[j] +
                  cs[m * 3 + 1] * bff[128 + j] +
                  cs[m * 3 + 2] * bff[256 + j];
        float f = t - rintf(t);
        float ang = TWO_PI_F * f;
        store1(p0, j, m, __sinf(ang));
        store1(p0, 128 + j, m, __cosf(ang));
    }
    __syncthreads();

    // layer 0: K=256, P0 -> P1
    run_layer<16>(p1, p0u, g_wfrag, b_first, wid, lane);
    // hidden layers: K=512, alternate planes (l even: P1->P0, odd: P0->P1)
#pragma unroll 1
    for (int l = 0; l < 5; ++l) {
        const size_t base = (size_t)(512 + l * 1024) * 128;
        unsigned char* dst = (l & 1) ? p1 : p0;
        uint32_t src = (l & 1) ? p0u : p1u;
        run_layer<32>(dst, src, g_wfrag + base,
                      b_hidden + l * 512, wid, lane);
    }
    // after 5 hidden layers (l=0..4): final activations in P0

    // ---- output linear 512 -> 3: 256 threads, 4 k-slices per point ----
    for (int f = tid; f < 1536; f += THREADS) wout[f] = W_out[f];
    __syncthreads();
    {
        const int p = tid >> 2;        // point 0..63
        const int s = tid & 3;         // k-slice 0..3
        float a0 = 0.0f, a1 = 0.0f, a2 = 0.0f;
#pragma unroll 4
        for (int kk = 0; kk < 128; ++kk) {
            const int k = s * 128 + kk;
            uint32_t off = (uint32_t)k * 128u +
                           (((uint32_t)p * 2u) ^ (((uint32_t)k & 7u) << 4));
            float hv = hff(*(uint16_t*)(p0 + off));
            a0 = fmaf(hv, wout[k], a0);
            a1 = fmaf(hv, wout[512 + k], a1);
            a2 = fmaf(hv, wout[1024 + k], a2);
        }
#pragma unroll
        for (int d = 2; d >= 1; d >>= 1) {
            a0 += __shfl_down_sync(0xFFFFFFFFu, a0, d, 4);
            a1 += __shfl_down_sync(0xFFFFFFFFu, a1, d, 4);
            a2 += __shfl_down_sync(0xFFFFFFFFu, a2, d, 4);
        }
        if (s == 0) {
            int gp = pt0 + p;
            if (gp < L) {
                out[gp * 3 + 0] = a0 + __ldg(b_out + 0);
                out[gp * 3 + 1] = a1 + __ldg(b_out + 1);
                out[gp * 3 + 2] = a2 + __ldg(b_out + 2);
            }
        }
    }
}

// ---------------- launcher ----------------
extern "C" void kernel_launch(void* const* d_in, const int* in_sizes, int n_in,
                              void* d_out, int out_size) {
    const float* coords   = (const float*)d_in[0];
    const float* B_ff     = (const float*)d_in[1];
    const float* W_first  = (const float*)d_in[2];
    const float* b_first  = (const float*)d_in[3];
    const float* W_hidden = (const float*)d_in[4];
    const float* b_hidden = (const float*)d_in[5];
    const float* W_out    = (const float*)d_in[6];
    const float* b_out    = (const float*)d_in[7];
    float* out = (float*)d_out;

    int L = in_sizes[0] / 3;
    int tiles = (L + 63) / 64;

    prep_weights<<<(PLANE_U32 + 255) / 256, 256>>>(W_first, W_hidden);

    cudaFuncSetAttribute(inr_mma_kernel,
                         cudaFuncAttributeMaxDynamicSharedMemorySize,
                         SMEM_BYTES);
    inr_mma_kernel<<<tiles, THREADS, SMEM_BYTES>>>(
        coords, B_ff, b_first, b_hidden, W_out, b_out, out, L);
}

// round 15
// speedup vs baseline: 1.0318x; 1.0318x over previous
#include <cuda_runtime.h>
#include <cuda_fp16.h>
#include <math.h>
#include <stdint.h>

// ===========================================================================
// Fused INR via warp-level mma.sync, fp16 weights/acts, fp32 accum.
// R14: CTA split into two independent named-barrier halves (warps 0-3 =
//      points 0-31, warps 4-7 = points 32-63; barrier ids 1/2). Each SMSP
//      holds one warp of each half, so one half's sin/FF/out phases overlap
//      the other half's MMA stream. Warp = 128 neurons x 32 pts (8mt x 4nt).
// ===========================================================================

#define OMEGA0    30.0f
#define TWO_PI_F  6.283185307179586f
#define THREADS   256

#define NTILES    (512 + 5 * 1024)      // 5632 (mt,ks) tiles total
#define PLANE_U32 (NTILES * 128)        // u32 per plane (tile=128 u32)

__device__ __align__(16) uint32_t g_wfrag[PLANE_U32];   // fp16 weight fragments

// ---- SMEM layout (bytes) ----
#define SM_WOUT  0                       // 1536 floats
#define SM_CS    6144                    // 192 floats
#define SM_BFF   6912                    // 384 floats
#define SM_P0    9216                    // act plane 0: 512 rows x 128B
#define SM_P1    (SM_P0 + 65536)         // act plane 1
#define SMEM_BYTES (SM_P1 + 65536)       // 140288

// ---------------- helpers ----------------
__device__ __forceinline__ uint32_t smem_u32(const void* p) {
    uint32_t a;
    asm("{ .reg .u64 t; cvta.to.shared.u64 t, %1; cvt.u32.u64 %0, t; }"
        : "=r"(a) : "l"(p));
    return a;
}
__device__ __forceinline__ void barh(int half) {   // per-half named barrier
    asm volatile("bar.sync %0, 128;" :: "r"(1 + half) : "memory");
}
__device__ __forceinline__ void mma16816(float* d, const uint4& a,
                                         uint32_t b0, uint32_t b1) {
    asm volatile(
        "mma.sync.aligned.m16n8k16.row.col.f32.f16.f16.f32 "
        "{%0,%1,%2,%3}, {%4,%5,%6,%7}, {%8,%9}, {%0,%1,%2,%3};"
        : "+f"(d[0]), "+f"(d[1]), "+f"(d[2]), "+f"(d[3])
        : "r"(a.x), "r"(a.y), "r"(a.z), "r"(a.w), "r"(b0), "r"(b1));
}
__device__ __forceinline__ void ldmx4t(uint32_t& r0, uint32_t& r1,
                                       uint32_t& r2, uint32_t& r3,
                                       uint32_t addr) {
    asm volatile(
        "ldmatrix.sync.aligned.m8n8.x4.trans.shared.b16 {%0,%1,%2,%3}, [%4];"
        : "=r"(r0), "=r"(r1), "=r"(r2), "=r"(r3) : "r"(addr));
}
__device__ __forceinline__ uint16_t hfb(float v) {
    __half h = __float2half_rn(v);
    return *reinterpret_cast<uint16_t*>(&h);
}
__device__ __forceinline__ float hff(uint16_t b) {
    __half h = *reinterpret_cast<__half*>(&b);
    return __half2float(h);
}

// store v (fp16) to (row, col n) in a plane, swizzled
__device__ __forceinline__ void store1(unsigned char* plane, int row, int n, float v) {
    uint32_t off = (uint32_t)row * 128u + (((uint32_t)n * 2u) ^ (((uint32_t)row & 7u) << 4));
    *(uint16_t*)(plane + off) = hfb(v);
}

// ---------------- weight prep: fp32 -> fragment-ordered fp16 ----------------
__global__ void prep_weights(const float* __restrict__ Wf,
                             const float* __restrict__ Wh) {
    int idx = blockIdx.x * blockDim.x + threadIdx.x;
    if (idx >= PLANE_U32) return;
    int tile = idx >> 7;
    int li   = idx & 127;
    int lane = li >> 2, q = li & 3;

    const float* src; int K, mt, ks;
    if (tile < 512) { mt = tile >> 4; ks = tile & 15; K = 256; src = Wf; }
    else {
        int th = tile - 512;
        int l = th >> 10, tt = th & 1023;
        mt = tt >> 5; ks = tt & 31; K = 512;
        src = Wh + (size_t)l * 512 * 512;
    }
    int r  = lane >> 2, c2 = (lane & 3) * 2;
    int row = mt * 16 + r + (q & 1) * 8;
    int k   = ks * 16 + c2 + (q >> 1) * 8;
    float w0 = src[(size_t)row * K + k];
    float w1 = src[(size_t)row * K + k + 1];
    g_wfrag[idx] = ((uint32_t)hfb(w1) << 16) | (uint32_t)hfb(w0);
}

// ---------------- one sine layer (per half): src plane -> dst plane --------
template <int KS>
__device__ __forceinline__ void run_layer(
    unsigned char* dst, uint32_t src_u32,
    const uint32_t* __restrict__ whi,
    const float* __restrict__ bias,
    int hw, int half, int lane)
{
    float acc[8][4][4];     // [m-tile][n-tile][frag]
#pragma unroll
    for (int a = 0; a < 8; ++a)
#pragma unroll
        for (int b = 0; b < 4; ++b)
#pragma unroll
            for (int c = 0; c < 4; ++c) acc[a][b][c] = 0.0f;

    const int r  = lane >> 2;
    const int cq = lane & 3;
    const int mid  = lane >> 3;
    const int rrow = lane & 7;
    const uint32_t rswz = (uint32_t)rrow << 4;
    const uint32_t krow_off = ((uint32_t)((mid & 1) * 8 + rrow)) * 128u;
    const uint32_t nb_base  = (uint32_t)((mid >> 1) * 8) * 2u + (uint32_t)half * 64u;

    const uint32_t* pA[8];
#pragma unroll
    for (int mt = 0; mt < 8; ++mt)
        pA[mt] = whi + (size_t)((hw * 8 + mt) * KS) * 128 + lane * 4;

    uint32_t baddr[2];
#pragma unroll
    for (int j = 0; j < 2; ++j)
        baddr[j] = src_u32 + krow_off + (((uint32_t)j * 32u + nb_base) ^ rswz);

    // prologue: A and B for ks=0
    uint4 A[8], nA[8];
#pragma unroll
    for (int mt = 0; mt < 8; ++mt) A[mt] = *(const uint4*)pA[mt];
    uint32_t B0[8], B1[8];
#pragma unroll
    for (int j = 0; j < 2; ++j)
        ldmx4t(B0[4 * j], B0[4 * j + 1], B0[4 * j + 2], B0[4 * j + 3],
               baddr[j]);

#pragma unroll 1
    for (int ks = 0; ks < KS; ks += 2) {
        // ---- even step: prefetch A(ks+1), B(ks+1); MMA on A,B0 ----
#pragma unroll
        for (int mt = 0; mt < 8; ++mt)
            nA[mt] = *(const uint4*)(pA[mt] + (ks + 1) * 128);
        {
            const uint32_t kb = (uint32_t)(ks + 1) * 2048u;
#pragma unroll
            for (int j = 0; j < 2; ++j)
                ldmx4t(B1[4 * j], B1[4 * j + 1], B1[4 * j + 2], B1[4 * j + 3],
                       baddr[j] + kb);
        }
#pragma unroll
        for (int nt = 0; nt < 4; ++nt)
#pragma unroll
            for (int mt = 0; mt < 8; ++mt)
                mma16816(acc[mt][nt], A[mt], B0[nt * 2], B0[nt * 2 + 1]);

        // ---- odd step: prefetch A(ks+2), B(ks+2); MMA on nA,B1 ----
        if (ks + 2 < KS) {
#pragma unroll
            for (int mt = 0; mt < 8; ++mt)
                A[mt] = *(const uint4*)(pA[mt] + (ks + 2) * 128);
            const uint32_t kb = (uint32_t)(ks + 2) * 2048u;
#pragma unroll
            for (int j = 0; j < 2; ++j)
                ldmx4t(B0[4 * j], B0[4 * j + 1], B0[4 * j + 2], B0[4 * j + 3],
                       baddr[j] + kb);
        }
#pragma unroll
        for (int nt = 0; nt < 4; ++nt)
#pragma unroll
            for (int mt = 0; mt < 8; ++mt)
                mma16816(acc[mt][nt], nA[mt], B1[nt * 2], B1[nt * 2 + 1]);
    }

    // ---- epilogue: sin -> f16x2 pack -> STS to dst (own columns only) ----
#pragma unroll
    for (int mtl = 0; mtl < 8; ++mtl) {
        const int row0 = (hw * 8 + mtl) * 16 + r;
        const int row1 = row0 + 8;
        const float ob0 = OMEGA0 * __ldg(bias + row0);
        const float ob1 = OMEGA0 * __ldg(bias + row1);
        const uint32_t sw0 = ((uint32_t)row0 & 7u) << 4;
        const uint32_t sw1 = ((uint32_t)row1 & 7u) << 4;
#pragma unroll
        for (int nt = 0; nt < 4; ++nt) {
            const int n = half * 32 + nt * 8 + cq * 2;
            float v00 = __sinf(fmaf(OMEGA0, acc[mtl][nt][0], ob0));
            float v01 = __sinf(fmaf(OMEGA0, acc[mtl][nt][1], ob0));
            float v10 = __sinf(fmaf(OMEGA0, acc[mtl][nt][2], ob1));
            float v11 = __sinf(fmaf(OMEGA0, acc[mtl][nt][3], ob1));
            uint32_t hp0, hp1;
            asm("cvt.rn.f16x2.f32 %0, %1, %2;"
                : "=r"(hp0) : "f"(v01), "f"(v00));
            asm("cvt.rn.f16x2.f32 %0, %1, %2;"
                : "=r"(hp1) : "f"(v11), "f"(v10));
            uint32_t off0 = (uint32_t)row0 * 128u + (((uint32_t)n * 2u) ^ sw0);
            uint32_t off1 = (uint32_t)row1 * 128u + (((uint32_t)n * 2u) ^ sw1);
            *(uint32_t*)(dst + off0) = hp0;
            *(uint32_t*)(dst + off1) = hp1;
        }
    }
    barh(half);   // half-local: dst columns visible; src columns reusable
}

// ---------------- main kernel ----------------
__global__ void __launch_bounds__(THREADS, 1)
inr_mma_kernel(const float* __restrict__ coords,
               const float* __restrict__ B_ff,
               const float* __restrict__ b_first,
               const float* __restrict__ b_hidden,
               const float* __restrict__ W_out,
               const float* __restrict__ b_out,
               float* __restrict__ out, int L)
{
    extern __shared__ unsigned char sm[];
    float* wout = (float*)(sm + SM_WOUT);
    float* cs   = (float*)(sm + SM_CS);
    float* bff  = (float*)(sm + SM_BFF);
    unsigned char* p0 = sm + SM_P0;
    unsigned char* p1 = sm + SM_P1;
    const uint32_t p0u = smem_u32(p0);
    const uint32_t p1u = smem_u32(p1);

    const int tid  = threadIdx.x;
    const int wid  = tid >> 5;
    const int lane = tid & 31;
    const int half = wid >> 2;       // 0: points 0-31, 1: points 32-63
    const int hw   = wid & 3;        // warp within half
    const int ltid = tid & 127;      // thread within half
    const int pt0  = blockIdx.x * 64;

    if (tid < 192) {
        int g = pt0 * 3 + tid;
        cs[tid] = (g < L * 3) ? coords[g] : 0.0f;
    }
    for (int i = tid; i < 384; i += THREADS) bff[i] = B_ff[i];
    __syncthreads();   // shared staging visible to both halves

    // Fourier features -> plane 0, own 32 columns only.
    for (int e = ltid; e < 4096; e += 128) {
        int j = e >> 5, ml = e & 31;
        int m = half * 32 + ml;
        float t = cs[m * 3 + 0] * bff[j] +
                  cs[m * 3 + 1] * bff[128 + j] +
                  cs[m * 3 + 2] * bff[256 + j];
        float f = t - rintf(t);
        float ang = TWO_PI_F * f;
        store1(p0, j, m, __sinf(ang));
        store1(p0, 128 + j, m, __cosf(ang));
    }
    barh(half);

    // layer 0: K=256, P0 -> P1
    run_layer<16>(p1, p0u, g_wfrag, b_first, hw, half, lane);
    // hidden layers: K=512, alternate planes (l even: P1->P0, odd: P0->P1)
#pragma unroll 1
    for (int l = 0; l < 5; ++l) {
        const size_t base = (size_t)(512 + l * 1024) * 128;
        unsigned char* dst = (l & 1) ? p1 : p0;
        uint32_t src = (l & 1) ? p0u : p1u;
        run_layer<32>(dst, src, g_wfrag + base,
                      b_hidden + l * 512, hw, half, lane);
    }
    // final activations in P0

    // ---- output linear 512 -> 3 (per half; redundant wout load is benign) --
    for (int f = ltid; f < 1536; f += 128) wout[f] = W_out[f];
    barh(half);
    {
        const int pl = ltid >> 2;      // local point 0..31
        const int s  = ltid & 3;       // k-slice 0..3
        const int p  = half * 32 + pl;
        float a0 = 0.0f, a1 = 0.0f, a2 = 0.0f;
#pragma unroll 4
        for (int kk = 0; kk < 128; ++kk) {
            const int k = s * 128 + kk;
            uint32_t off = (uint32_t)k * 128u +
                           (((uint32_t)p * 2u) ^ (((uint32_t)k & 7u) << 4));
            float hv = hff(*(uint16_t*)(p0 + off));
            a0 = fmaf(hv, wout[k], a0);
            a1 = fmaf(hv, wout[512 + k], a1);
            a2 = fmaf(hv, wout[1024 + k], a2);
        }
#pragma unroll
        for (int d = 2; d >= 1; d >>= 1) {
            a0 += __shfl_down_sync(0xFFFFFFFFu, a0, d, 4);
            a1 += __shfl_down_sync(0xFFFFFFFFu, a1, d, 4);
            a2 += __shfl_down_sync(0xFFFFFFFFu, a2, d, 4);
        }
        if (s == 0) {
            int gp = pt0 + p;
            if (gp < L) {
                out[gp * 3 + 0] = a0 + __ldg(b_out + 0);
                out[gp * 3 + 1] = a1 + __ldg(b_out + 1);
                out[gp * 3 + 2] = a2 + __ldg(b_out + 2);
            }
        }
    }
}

// ---------------- launcher ----------------
extern "C" void kernel_launch(void* const* d_in, const int* in_sizes, int n_in,
                              void* d_out, int out_size) {
    const float* coords   = (const float*)d_in[0];
    const float* B_ff     = (const float*)d_in[1];
    const float* W_first  = (const float*)d_in[2];
    const float* b_first  = (const float*)d_in[3];
    const float* W_hidden = (const float*)d_in[4];
    const float* b_hidden = (const float*)d_in[5];
    const float* W_out    = (const float*)d_in[6];
    const float* b_out    = (const float*)d_in[7];
    float* out = (float*)d_out;

    int L = in_sizes[0] / 3;
    int tiles = (L + 63) / 64;

    prep_weights<<<(PLANE_U32 + 255) / 256, 256>>>(W_first, W_hidden);

    cudaFuncSetAttribute(inr_mma_kernel,
                         cudaFuncAttributeMaxDynamicSharedMemorySize,
                         SMEM_BYTES);
    inr_mma_kernel<<<tiles, THREADS, SMEM_BYTES>>>(
        coords, B_ff, b_first, b_hidden, W_out, b_out, out, L);
}

// round 16
// speedup vs baseline: 1.0812x; 1.0478x over previous
#include <cuda_runtime.h>
#include <cuda_fp16.h>
#include <math.h>
#include <stdint.h>

// ===========================================================================
// Fused INR via warp-level mma.sync, fp16 weights/acts, fp32 accum.
// R15 = R12 (8 warps, warp = 64 neurons x 64 pts, 1-step A prefetch,
//       B double-buffer) + persistent CTAs: grid = #SMs, in-kernel tile loop,
//       bff/W_out staged once, next tile's coords prefetched under out-phase.
// ===========================================================================

#define OMEGA0    30.0f
#define TWO_PI_F  6.283185307179586f
#define THREADS   256

#define NTILES    (512 + 5 * 1024)      // 5632 (mt,ks) tiles total
#define PLANE_U32 (NTILES * 128)        // u32 per plane (tile=128 u32)

__device__ __align__(16) uint32_t g_wfrag[PLANE_U32];   // fp16 weight fragments

// ---- SMEM layout (bytes) ----
#define SM_WOUT  0                       // 1536 floats
#define SM_CS    6144                    // 192 floats
#define SM_BFF   6912                    // 384 floats
#define SM_P0    9216                    // act plane 0: 512 rows x 128B
#define SM_P1    (SM_P0 + 65536)         // act plane 1
#define SMEM_BYTES (SM_P1 + 65536)       // 140288

// ---------------- helpers ----------------
__device__ __forceinline__ uint32_t smem_u32(const void* p) {
    uint32_t a;
    asm("{ .reg .u64 t; cvta.to.shared.u64 t, %1; cvt.u32.u64 %0, t; }"
        : "=r"(a) : "l"(p));
    return a;
}
__device__ __forceinline__ void mma16816(float* d, const uint4& a,
                                         uint32_t b0, uint32_t b1) {
    asm volatile(
        "mma.sync.aligned.m16n8k16.row.col.f32.f16.f16.f32 "
        "{%0,%1,%2,%3}, {%4,%5,%6,%7}, {%8,%9}, {%0,%1,%2,%3};"
        : "+f"(d[0]), "+f"(d[1]), "+f"(d[2]), "+f"(d[3])
        : "r"(a.x), "r"(a.y), "r"(a.z), "r"(a.w), "r"(b0), "r"(b1));
}
__device__ __forceinline__ void ldmx4t(uint32_t& r0, uint32_t& r1,
                                       uint32_t& r2, uint32_t& r3,
                                       uint32_t addr) {
    asm volatile(
        "ldmatrix.sync.aligned.m8n8.x4.trans.shared.b16 {%0,%1,%2,%3}, [%4];"
        : "=r"(r0), "=r"(r1), "=r"(r2), "=r"(r3) : "r"(addr));
}
__device__ __forceinline__ uint16_t hfb(float v) {
    __half h = __float2half_rn(v);
    return *reinterpret_cast<uint16_t*>(&h);
}
__device__ __forceinline__ float hff(uint16_t b) {
    __half h = *reinterpret_cast<__half*>(&b);
    return __half2float(h);
}

// store v (fp16) to (row, col n) in a plane, swizzled
__device__ __forceinline__ void store1(unsigned char* plane, int row, int n, float v) {
    uint32_t off = (uint32_t)row * 128u + (((uint32_t)n * 2u) ^ (((uint32_t)row & 7u) << 4));
    *(uint16_t*)(plane + off) = hfb(v);
}

// ---------------- weight prep: fp32 -> fragment-ordered fp16 ----------------
__global__ void prep_weights(const float* __restrict__ Wf,
                             const float* __restrict__ Wh) {
    int idx = blockIdx.x * blockDim.x + threadIdx.x;
    if (idx >= PLANE_U32) return;
    int tile = idx >> 7;
    int li   = idx & 127;
    int lane = li >> 2, q = li & 3;

    const float* src; int K, mt, ks;
    if (tile < 512) { mt = tile >> 4; ks = tile & 15; K = 256; src = Wf; }
    else {
        int th = tile - 512;
        int l = th >> 10, tt = th & 1023;
        mt = tt >> 5; ks = tt & 31; K = 512;
        src = Wh + (size_t)l * 512 * 512;
    }
    int r  = lane >> 2, c2 = (lane & 3) * 2;
    int row = mt * 16 + r + (q & 1) * 8;
    int k   = ks * 16 + c2 + (q >> 1) * 8;
    float w0 = src[(size_t)row * K + k];
    float w1 = src[(size_t)row * K + k + 1];
    g_wfrag[idx] = ((uint32_t)hfb(w1) << 16) | (uint32_t)hfb(w0);
}

// ---------------- one sine layer: src plane -> dst plane ----------------
template <int KS>
__device__ __forceinline__ void run_layer(
    unsigned char* dst, uint32_t src_u32,
    const uint32_t* __restrict__ whi,
    const float* __restrict__ bias,
    int wid, int lane)
{
    float acc[4][8][4];     // [m-tile][n-tile][frag]
#pragma unroll
    for (int a = 0; a < 4; ++a)
#pragma unroll
        for (int b = 0; b < 8; ++b)
#pragma unroll
            for (int c = 0; c < 4; ++c) acc[a][b][c] = 0.0f;

    const int r  = lane >> 2;
    const int cq = lane & 3;
    const int mid  = lane >> 3;
    const int rrow = lane & 7;
    const uint32_t rswz = (uint32_t)rrow << 4;
    const uint32_t krow_off = ((uint32_t)((mid & 1) * 8 + rrow)) * 128u;
    const uint32_t nb_base  = (uint32_t)((mid >> 1) * 8) * 2u;

    const uint32_t* pA[4];
#pragma unroll
    for (int mt = 0; mt < 4; ++mt)
        pA[mt] = whi + (size_t)((wid * 4 + mt) * KS) * 128 + lane * 4;

    uint32_t baddr[4];
#pragma unroll
    for (int j = 0; j < 4; ++j)
        baddr[j] = src_u32 + krow_off + (((uint32_t)j * 32u + nb_base) ^ rswz);

    // prologue: A and B for ks=0
    uint4 A[4], nA[4];
#pragma unroll
    for (int mt = 0; mt < 4; ++mt) A[mt] = *(const uint4*)pA[mt];
    uint32_t B0[16], B1[16];
#pragma unroll
    for (int j = 0; j < 4; ++j)
        ldmx4t(B0[4 * j], B0[4 * j + 1], B0[4 * j + 2], B0[4 * j + 3],
               baddr[j]);

#pragma unroll 1
    for (int ks = 0; ks < KS; ks += 2) {
        // ---- even step: prefetch A(ks+1), B(ks+1); MMA on A,B0 ----
#pragma unroll
        for (int mt = 0; mt < 4; ++mt)
            nA[mt] = *(const uint4*)(pA[mt] + (ks + 1) * 128);
        {
            const uint32_t kb = (uint32_t)(ks + 1) * 2048u;
#pragma unroll
            for (int j = 0; j < 4; ++j)
                ldmx4t(B1[4 * j], B1[4 * j + 1], B1[4 * j + 2], B1[4 * j + 3],
                       baddr[j] + kb);
        }
#pragma unroll
        for (int nt = 0; nt < 8; ++nt)
#pragma unroll
            for (int mt = 0; mt < 4; ++mt)
                mma16816(acc[mt][nt], A[mt], B0[nt * 2], B0[nt * 2 + 1]);

        // ---- odd step: prefetch A(ks+2), B(ks+2); MMA on nA,B1 ----
        if (ks + 2 < KS) {
#pragma unroll
            for (int mt = 0; mt < 4; ++mt)
                A[mt] = *(const uint4*)(pA[mt] + (ks + 2) * 128);
            const uint32_t kb = (uint32_t)(ks + 2) * 2048u;
#pragma unroll
            for (int j = 0; j < 4; ++j)
                ldmx4t(B0[4 * j], B0[4 * j + 1], B0[4 * j + 2], B0[4 * j + 3],
                       baddr[j] + kb);
        }
#pragma unroll
        for (int nt = 0; nt < 8; ++nt)
#pragma unroll
            for (int mt = 0; mt < 4; ++mt)
                mma16816(acc[mt][nt], nA[mt], B1[nt * 2], B1[nt * 2 + 1]);
    }

    // ---- epilogue: sin -> f16x2 pack -> STS to dst ----
#pragma unroll
    for (int mtl = 0; mtl < 4; ++mtl) {
        const int row0 = wid * 64 + mtl * 16 + r;
        const int row1 = row0 + 8;
        const float ob0 = OMEGA0 * __ldg(bias + row0);
        const float ob1 = OMEGA0 * __ldg(bias + row1);
        const uint32_t sw0 = ((uint32_t)row0 & 7u) << 4;
        const uint32_t sw1 = ((uint32_t)row1 & 7u) << 4;
#pragma unroll
        for (int nt = 0; nt < 8; ++nt) {
            const int n = nt * 8 + cq * 2;
            float v00 = __sinf(fmaf(OMEGA0, acc[mtl][nt][0], ob0));
            float v01 = __sinf(fmaf(OMEGA0, acc[mtl][nt][1], ob0));
            float v10 = __sinf(fmaf(OMEGA0, acc[mtl][nt][2], ob1));
            float v11 = __sinf(fmaf(OMEGA0, acc[mtl][nt][3], ob1));
            uint32_t hp0, hp1;
            asm("cvt.rn.f16x2.f32 %0, %1, %2;"
                : "=r"(hp0) : "f"(v01), "f"(v00));
            asm("cvt.rn.f16x2.f32 %0, %1, %2;"
                : "=r"(hp1) : "f"(v11), "f"(v10));
            uint32_t off0 = (uint32_t)row0 * 128u + (((uint32_t)n * 2u) ^ sw0);
            uint32_t off1 = (uint32_t)row1 * 128u + (((uint32_t)n * 2u) ^ sw1);
            *(uint32_t*)(dst + off0) = hp0;
            *(uint32_t*)(dst + off1) = hp1;
        }
    }
    __syncthreads();   // dst visible; src free for reuse as next dst
}

// ---------------- main kernel (persistent) ----------------
__global__ void __launch_bounds__(THREADS, 1)
inr_mma_kernel(const float* __restrict__ coords,
               const float* __restrict__ B_ff,
               const float* __restrict__ b_first,
               const float* __restrict__ b_hidden,
               const float* __restrict__ W_out,
               const float* __restrict__ b_out,
               float* __restrict__ out, int L)
{
    extern __shared__ unsigned char sm[];
    float* wout = (float*)(sm + SM_WOUT);
    float* cs   = (float*)(sm + SM_CS);
    float* bff  = (float*)(sm + SM_BFF);
    unsigned char* p0 = sm + SM_P0;
    unsigned char* p1 = sm + SM_P1;
    const uint32_t p0u = smem_u32(p0);
    const uint32_t p1u = smem_u32(p1);

    const int tid  = threadIdx.x;
    const int wid  = tid >> 5;
    const int lane = tid & 31;
    const int tiles = (L + 63) >> 6;

    // ---- one-time staging: B_ff, W_out, coords of first tile ----
    for (int i = tid; i < 384; i += THREADS) bff[i] = B_ff[i];
    for (int f = tid; f < 1536; f += THREADS) wout[f] = W_out[f];
    if ((int)blockIdx.x < tiles && tid < 192) {
        int g = blockIdx.x * 192 + tid;
        cs[tid] = (g < L * 3) ? coords[g] : 0.0f;
    }
    __syncthreads();

#pragma unroll 1
    for (int t = blockIdx.x; t < tiles; t += gridDim.x) {
        const int pt0 = t * 64;

        // ---- Fourier features -> plane 0 (exact 2pi reduction) ----
        for (int e = tid; e < 8192; e += THREADS) {
            int j = e >> 6, m = e & 63;
            float tt = cs[m * 3 + 0] * bff[j] +
                       cs[m * 3 + 1] * bff[128 + j] +
                       cs[m * 3 + 2] * bff[256 + j];
            float f = tt - rintf(tt);
            float ang = TWO_PI_F * f;
            store1(p0, j, m, __sinf(ang));
            store1(p0, 128 + j, m, __cosf(ang));
        }
        __syncthreads();

        // ---- layers ----
        run_layer<16>(p1, p0u, g_wfrag, b_first, wid, lane);
#pragma unroll 1
        for (int l = 0; l < 5; ++l) {
            const size_t base = (size_t)(512 + l * 1024) * 128;
            unsigned char* dst = (l & 1) ? p1 : p0;
            uint32_t src = (l & 1) ? p0u : p1u;
            run_layer<32>(dst, src, g_wfrag + base,
                          b_hidden + l * 512, wid, lane);
        }
        // final activations in P0 (after run_layer's own __syncthreads)

        // ---- prefetch next tile's coords (overlaps out-phase FMA) ----
        {
            int nt = t + gridDim.x;
            if (nt < tiles && tid < 192) {
                int g = nt * 192 + tid;
                cs[tid] = (g < L * 3) ? coords[g] : 0.0f;
            }
        }

        // ---- output linear 512 -> 3: 4 k-slices per point ----
        {
            const int p = tid >> 2;        // point 0..63
            const int s = tid & 3;         // k-slice 0..3
            float a0 = 0.0f, a1 = 0.0f, a2 = 0.0f;
#pragma unroll 4
            for (int kk = 0; kk < 128; ++kk) {
                const int k = s * 128 + kk;
                uint32_t off = (uint32_t)k * 128u +
                               (((uint32_t)p * 2u) ^ (((uint32_t)k & 7u) << 4));
                float hv = hff(*(uint16_t*)(p0 + off));
                a0 = fmaf(hv, wout[k], a0);
                a1 = fmaf(hv, wout[512 + k], a1);
                a2 = fmaf(hv, wout[1024 + k], a2);
            }
#pragma unroll
            for (int d = 2; d >= 1; d >>= 1) {
                a0 += __shfl_down_sync(0xFFFFFFFFu, a0, d, 4);
                a1 += __shfl_down_sync(0xFFFFFFFFu, a1, d, 4);
                a2 += __shfl_down_sync(0xFFFFFFFFu, a2, d, 4);
            }
            if (s == 0) {
                int gp = pt0 + p;
                if (gp < L) {
                    out[gp * 3 + 0] = a0 + __ldg(b_out + 0);
                    out[gp * 3 + 1] = a1 + __ldg(b_out + 1);
                    out[gp * 3 + 2] = a2 + __ldg(b_out + 2);
                }
            }
        }
        __syncthreads();   // out reads of P0 done; cs staged; next FF may run
    }
}

// ---------------- launcher ----------------
extern "C" void kernel_launch(void* const* d_in, const int* in_sizes, int n_in,
                              void* d_out, int out_size) {
    const float* coords   = (const float*)d_in[0];
    const float* B_ff     = (const float*)d_in[1];
    const float* W_first  = (const float*)d_in[2];
    const float* b_first  = (const float*)d_in[3];
    const float* W_hidden = (const float*)d_in[4];
    const float* b_hidden = (const float*)d_in[5];
    const float* W_out    = (const float*)d_in[6];
    const float* b_out    = (const float*)d_in[7];
    float* out = (float*)d_out;

    int L = in_sizes[0] / 3;
    int tiles = (L + 63) / 64;
    int blocks = tiles < 152 ? tiles : 152;   // GB300: 152 SMs, 1 CTA/SM

    prep_weights<<<(PLANE_U32 + 255) / 256, 256>>>(W_first, W_hidden);

    cudaFuncSetAttribute(inr_mma_kernel,
                         cudaFuncAttributeMaxDynamicSharedMemorySize,
                         SMEM_BYTES);
    inr_mma_kernel<<<blocks, THREADS, SMEM_BYTES>>>(
        coords, B_ff, b_first, b_hidden, W_out, b_out, out, L);
}